// round 17
// baseline (speedup 1.0000x reference)
#include <cuda_runtime.h>
#include <cuda_fp16.h>
#include <math.h>
#include <cstdint>

// ---------------------------------------------------------------------------
// DAFCN forward, B=1024, T=50, F=48, D=512.
// Attention branch dead: combined[:,:,:10] = gcn_out only.
// R17: R16 + (1) coalesced epilogue finish via SMEM round-trip,
//      (2) layer3 emits fp16 only; tail consumes fp16 y,
//      (3) prep_w folded into head_kernel.
// ---------------------------------------------------------------------------

typedef unsigned long long ull;

#define PI_F 3.14159265358979f
#define W0_DCT 0.18257418583505537f
#define W1_DCT 0.2581988897471611f
#define NB 1024
#define MROWS (NB * 48)

__device__ float  g_X[MROWS * 512];       // fp32 y (residual carrier, layers 1)
__device__ __half g_Af[MROWS * 512];      // fp16 gemm A operand / final y2
__device__ __half g_Wh[4 * 512 * 512];    // W^T [l][n][k] fp16
__device__ float  g_dct[NB * 480];
__device__ float  g_ffc[NB * 480];

// ---- helpers --------------------------------------------------------------
__device__ __forceinline__ uint32_t smem_u32(const void* p) {
    uint32_t a;
    asm("{ .reg .u64 t; cvta.to.shared.u64 t, %1; cvt.u32.u64 %0, t; }"
        : "=r"(a) : "l"(p));
    return a;
}
__device__ __forceinline__ float ftanh(float x) {
    return 1.0f - __fdividef(2.0f, __expf(2.0f * x) + 1.0f);
}

#define CPA16(dst, src) \
    asm volatile("cp.async.cg.shared.global [%0], [%1], 16;" \
                 :: "r"(dst), "l"(src))
#define CP_COMMIT() asm volatile("cp.async.commit_group;" ::: "memory")
#define CP_WAIT(n)  asm volatile("cp.async.wait_group %0;" :: "n"(n) : "memory")

#define LDSM4(r, addr) \
    asm volatile("ldmatrix.sync.aligned.m8n8.x4.shared.b16 {%0,%1,%2,%3}, [%4];" \
        : "=r"((r)[0]), "=r"((r)[1]), "=r"((r)[2]), "=r"((r)[3]) : "r"(addr))

__device__ __forceinline__ void mma_f16(float* d, const uint32_t* a,
                                        const uint32_t* b) {
    asm volatile(
        "mma.sync.aligned.m16n8k16.row.col.f32.f16.f16.f32 "
        "{%0,%1,%2,%3}, {%4,%5,%6,%7}, {%8,%9}, {%0,%1,%2,%3};"
        : "+f"(d[0]), "+f"(d[1]), "+f"(d[2]), "+f"(d[3])
        : "r"(a[0]), "r"(a[1]), "r"(a[2]), "r"(a[3]), "r"(b[0]), "r"(b[1]));
}

// ======================= head: W-prep + FFC + gc1 (1 block / batch) ========
__global__ void __launch_bounds__(512)
head_kernel(const float* __restrict__ seq,
            const float* __restrict__ wl,  const float* __restrict__ wg,
            const float* __restrict__ gc1_w, const float* __restrict__ gc1_att,
            const float* __restrict__ gc1_b, const float* __restrict__ gcb_w) {
    __shared__ float sSeq[2400];
    __shared__ float sc[60], ss[60];
    __shared__ float sV[16][6][31];
    __shared__ float sWg[36], sWl[9];
    __shared__ float sDct[480], sZ1[480];

    const int tid = threadIdx.x, b = blockIdx.x;

    // ---- folded prep_w: this block converts 1024 W elements ----
    #pragma unroll
    for (int it = 0; it < 2; it++) {
        int idx = b * 1024 + it * 512 + tid;
        int l = idx >> 18, k = (idx >> 9) & 511, n = idx & 511;
        float w = gcb_w[l * 262144 + k * 512 + n];
        g_Wh[l * 262144 + n * 512 + k] = __float2half_rn(w);
    }

    for (int i = tid; i < 2400; i += 512) sSeq[i] = seq[b * 2400 + i];
    if (tid < 60) {
        float a = 6.283185307179586f * (float)tid / 60.0f;
        sc[tid] = cosf(a); ss[tid] = sinf(a);
    }
    if (tid < 36) sWg[tid] = wg[tid];
    if (tid < 9)  sWl[tid] = wl[tid];
    __syncthreads();

    if ((tid & 31) < 31) {
        const int g = tid >> 5, k = tid & 31;
        float re0=0,re1=0,re2=0,im0=0,im1=0,im2=0;
        int idx = 0;
        for (int t = 0; t < 60; t++) {
            int tsrc = (t < 50) ? t : 49;
            float co = sc[idx], si = ss[idx];
            float x0 = sSeq[tsrc * 48 + g];
            float x1 = sSeq[tsrc * 48 + 16 + g];
            float x2 = sSeq[tsrc * 48 + 32 + g];
            re0 += x0*co; im0 -= x0*si;
            re1 += x1*co; im1 -= x1*si;
            re2 += x2*co; im2 -= x2*si;
            idx += k; if (idx >= 60) idx -= 60;
        }
        float U[6] = {re0, re1, re2, im0, im1, im2};
        #pragma unroll
        for (int o = 0; o < 6; o++) {
            float a = 0.f;
            #pragma unroll
            for (int c = 0; c < 6; c++) a += sWg[o * 6 + c] * U[c];
            sV[g][o][k] = (a > 0.f) ? a : 0.f;
        }
    }
    __syncthreads();

    if (tid < 480) {
        const int g = tid / 30, r = tid % 30, o = r / 10, t = r % 10;
        float spec = sV[g][o][0] + ((t & 1) ? -sV[g][o][30] : sV[g][o][30]);
        int idx = t;
        for (int k = 1; k < 30; k++) {
            spec += 2.0f * (sV[g][o][k] * sc[idx] - sV[g][o + 3][k] * ss[idx]);
            idx += t; if (idx >= 60) idx -= 60;
        }
        float v = spec * (1.0f / 60.0f);
        #pragma unroll
        for (int c = 0; c < 3; c++) v += sWl[o * 3 + c] * sSeq[t * 48 + c * 16 + g];
        g_ffc[b * 480 + (o * 16 + g) * 10 + t] = v;
    }

    if (tid < 480) {
        int f = tid % 48, d = tid / 48;
        float wd = (d == 0) ? W0_DCT : W1_DCT;
        float acc = 0.f, Sd = 0.f;
        for (int k = 0; k < 30; k++) {
            float cv = wd * cosf(PI_F * ((float)k + 0.5f) * (float)d / 30.0f);
            if (k < 10) acc += cv * sSeq[(40 + k) * 48 + f];
            else        Sd  += cv;
        }
        acc += Sd * sSeq[49 * 48 + f];
        sDct[f * 10 + d] = acc;
        g_dct[b * 480 + f * 10 + d] = acc;
    }
    __syncthreads();
    if (tid < 480) {
        int n = tid / 10, d = tid % 10;
        float a = 0.f;
        for (int m = 0; m < 48; m++) a += __ldg(gc1_att + n * 48 + m) * sDct[m * 10 + d];
        sZ1[n * 10 + d] = a;
    }
    __syncthreads();
    {
        float w10[10];
        #pragma unroll
        for (int d = 0; d < 10; d++) w10[d] = __ldg(gc1_w + d * 512 + tid);
        float bb = __ldg(gc1_b + tid);
        for (int n = 0; n < 48; n++) {
            float a = bb;
            #pragma unroll
            for (int d = 0; d < 10; d++) a += w10[d] * sZ1[n * 10 + d];
            float v = ftanh(a);
            size_t idx = (size_t)(b * 48 + n) * 512 + tid;
            g_X[idx] = v;
            g_Af[idx] = __float2half_rn(v);
        }
    }
}

// ===========================================================================
// Layer kernel: fp16 HMMA mainloop (R12/R16 loader), tensor-core att epilogue
// with SMEM round-trip + fully coalesced final writes.
// ===========================================================================
#define ASTR 40
#define STG_A  (96  * ASTR * 2)        // 7680 B
#define STG_B  (128 * ASTR * 2)        // 10240 B
#define STG_SZ (STG_A + STG_B)         // 17920 B
#define GEMM_SMEM (4 * STG_SZ)         // 71680 B

__global__ void __launch_bounds__(256, 2)
layer_kernel(int layer, int residual, int emit, int write_x,
             const float* __restrict__ att, const float* __restrict__ bias) {
    extern __shared__ __align__(16) char smem[];
    const int tid = threadIdx.x;
    const int lane = tid & 31, wid = tid >> 5;
    const int wm = wid >> 2, wn = wid & 3;
    const int n0 = blockIdx.x * 128;
    const int m0 = blockIdx.y * 96;
    const uint32_t sbase = smem_u32(smem);

    const __half* Af = g_Af;
    const __half* Wh = g_Wh + layer * 262144;

    float acc[3][4][4];
    #pragma unroll
    for (int i = 0; i < 3; i++)
        #pragma unroll
        for (int j = 0; j < 4; j++)
            #pragma unroll
            for (int r = 0; r < 4; r++) acc[i][j][r] = 0.f;

    #define LOAD_STAGE(buf, ks) do { \
        uint32_t stg = sbase + (buf) * STG_SZ; \
        _Pragma("unroll") \
        for (int it = 0; it < 4; it++) { \
            int i = it * 256 + tid; \
            if (it == 3 && tid >= 128) break; \
            int r = i >> 2, q = i & 3; \
            uint32_t dst; const __half* src; \
            if (r < 96) { \
                dst = stg + r * 80 + q * 16; \
                src = Af + (size_t)(m0 + r) * 512 + (ks) * 32 + q * 8; \
            } else { \
                dst = stg + STG_A + (r - 96) * 80 + q * 16; \
                src = Wh + (size_t)(n0 + r - 96) * 512 + (ks) * 32 + q * 8; \
            } \
            CPA16(dst, src); \
        } \
    } while (0)

    LOAD_STAGE(0, 0); CP_COMMIT();
    LOAD_STAGE(1, 1); CP_COMMIT();
    LOAD_STAGE(2, 2); CP_COMMIT();

    const int arow = wm * 48 + (lane & 15);
    const int acol = (lane >> 4) * 8;
    const int brow = wn * 32 + (lane & 7) + ((lane >> 4) & 1) * 8;
    const int bcol = ((lane >> 3) & 1) * 8;

    int buf = 0, ld = 3;
    #pragma unroll 1
    for (int ks = 0; ks < 16; ks++) {
        if (ks + 3 < 16) {
            CP_WAIT(2);
            __syncthreads();
            LOAD_STAGE(ld, ks + 3);
            CP_COMMIT();
        } else {
            CP_WAIT(0);
            __syncthreads();
        }

        uint32_t base = sbase + buf * STG_SZ;
        #pragma unroll
        for (int sub = 0; sub < 2; sub++) {
            int kb = sub * 16;
            uint32_t ah[3][4], bh[2][4];
            #pragma unroll
            for (int mt = 0; mt < 3; mt++)
                LDSM4(ah[mt], base + (uint32_t)((arow + mt * 16) * ASTR + kb + acol) * 2);
            #pragma unroll
            for (int ng = 0; ng < 2; ng++)
                LDSM4(bh[ng], base + STG_A + (uint32_t)((brow + ng * 16) * ASTR + kb + bcol) * 2);
            #pragma unroll
            for (int mt = 0; mt < 3; mt++) {
                #pragma unroll
                for (int nf = 0; nf < 4; nf++)
                    mma_f16(acc[mt][nf], ah[mt], &bh[nf >> 1][(nf & 1) * 2]);
            }
        }
        __syncthreads();
        buf = (buf + 1) & 3;
        ld  = (ld  + 1) & 3;
    }

    // ========== epilogue: att@G on tensor cores ==========
    // sGt: [2][128 cols][64 halfs] (G transposed fp16) = 32768 B
    // sAtt: [48][64 halfs]                              =  6144 B
    __half* sGt  = (__half*)smem;
    __half* sAtt = (__half*)(smem + 32768);
    const uint32_t sGt_u  = sbase;
    const uint32_t sAtt_u = sbase + 32768;

    #pragma unroll
    for (int mt = 0; mt < 3; mt++) {
        int row = wm * 48 + mt * 16 + (lane >> 2);   // 0..95
        int b2 = row >= 48, ml = row - b2 * 48;
        #pragma unroll
        for (int nf = 0; nf < 4; nf++) {
            int col = wn * 32 + nf * 8 + (lane & 3) * 2;
            __half* p = sGt + (size_t)(b2 * 128 + col) * 64;
            p[ml]          = __float2half_rn(acc[mt][nf][0]);
            p[64 + ml]     = __float2half_rn(acc[mt][nf][1]);
            p[ml + 8]      = __float2half_rn(acc[mt][nf][2]);
            p[64 + ml + 8] = __float2half_rn(acc[mt][nf][3]);
        }
    }
    for (int i = tid; i < 2304; i += 256)
        sAtt[(i / 48) * 64 + (i % 48)] = __float2half_rn(__ldg(att + i));
    __syncthreads();

    // second MMA for both batches, raw outputs kept in regs
    float o_all[2][3][2][4];
    {
        const int c0 = wid * 16;
        const int ar2 = lane & 15;
        const int ac2 = (lane >> 4) * 8;
        const int br2 = (lane & 7) + ((lane >> 4) & 1) * 8;
        const int bc2 = ((lane >> 3) & 1) * 8;

        #pragma unroll
        for (int b2 = 0; b2 < 2; b2++) {
            #pragma unroll
            for (int mt = 0; mt < 3; mt++)
                #pragma unroll
                for (int nfi = 0; nfi < 2; nfi++)
                    #pragma unroll
                    for (int r = 0; r < 4; r++) o_all[b2][mt][nfi][r] = 0.f;

            #pragma unroll
            for (int kt = 0; kt < 3; kt++) {
                uint32_t af[3][4], bf[4];
                #pragma unroll
                for (int mt = 0; mt < 3; mt++)
                    LDSM4(af[mt], sAtt_u +
                          (uint32_t)((mt * 16 + ar2) * 64 + kt * 16 + ac2) * 2);
                LDSM4(bf, sGt_u +
                      (uint32_t)((b2 * 128 + c0 + br2) * 64 + kt * 16 + bc2) * 2);
                #pragma unroll
                for (int mt = 0; mt < 3; mt++) {
                    mma_f16(o_all[b2][mt][0], af[mt], &bf[0]);
                    mma_f16(o_all[b2][mt][1], af[mt], &bf[2]);
                }
            }
        }
    }
    __syncthreads();   // all sGt/sAtt reads done

    // scatter raw outputs to SMEM (padded rows, no gmem scatter)
    float* sO = (float*)smem;   // [96][132] = 50688 B
    {
        const int c0 = wid * 16;
        #pragma unroll
        for (int b2 = 0; b2 < 2; b2++) {
            #pragma unroll
            for (int mt = 0; mt < 3; mt++) {
                int nloc = mt * 16 + (lane >> 2);
                int row = b2 * 48 + nloc;
                #pragma unroll
                for (int nfi = 0; nfi < 2; nfi++) {
                    int col = c0 + nfi * 8 + (lane & 3) * 2;
                    sO[row * 132 + col]           = o_all[b2][mt][nfi][0];
                    sO[row * 132 + col + 1]       = o_all[b2][mt][nfi][1];
                    sO[(row + 8) * 132 + col]     = o_all[b2][mt][nfi][2];
                    sO[(row + 8) * 132 + col + 1] = o_all[b2][mt][nfi][3];
                }
            }
        }
    }
    __syncthreads();

    // coalesced finish: bias + tanh + residual + emit
    {
        const int lc = tid & 127;
        const int b2 = tid >> 7;
        const int col = n0 + lc;
        const float bb = __ldg(bias + col);
        #pragma unroll 4
        for (int n = 0; n < 48; n++) {
            float v = ftanh(sO[(b2 * 48 + n) * 132 + lc] + bb);
            size_t x = (size_t)(m0 + b2 * 48 + n) * 512 + col;
            if (residual) v += g_X[x];
            if (write_x) g_X[x] = v;
            if (emit) g_Af[x] = __float2half_rn(v);
        }
    }
}

// ======================= tail: gc7 + fused + MLP (fp16 y) ==================
// floats: sY/sH 12288 | sW7 5120 | sDct 480 | sP 480 | sOut 480 |
//         sFused 1920 | sW2 2560   (sYh = fp16 view of first region)
#define TAIL_SMEM ((12288 + 5120 + 480 + 480 + 480 + 1920 + 2560) * 4)
__global__ void __launch_bounds__(512)
tail_kernel(const float* __restrict__ gc7_w, const float* __restrict__ gc7_att,
            const float* __restrict__ gc7_b, const float* __restrict__ mlp_w1,
            const float* __restrict__ mlp_w2, float* __restrict__ out) {
    extern __shared__ float sm[];
    __half* sYh  = (__half*)sm;     // 24576 halfs (12288 float slots)
    float* sW7   = sm + 12288;      // 5120 [o][k]
    float* sDct  = sm + 17408;      // 480
    float* sP    = sm + 17888;      // 480
    float* sOut  = sm + 18368;      // 480
    float* sFused= sm + 18848;      // 1920
    float* sW2   = sm + 20768;      // 2560 [t2][o]
    float* sH    = sm;              // overlay (12288 floats) after P phase

    const int tid = threadIdx.x, b = blockIdx.x;
    const int lane = tid & 31, w = tid >> 5;

    {   // stage y2 (fp16) : 24576 halfs = 3072 float4
        const float4* ysrc = (const float4*)(g_Af + (size_t)b * 24576);
        float4* ydst = (float4*)sYh;
        #pragma unroll
        for (int i = 0; i < 6; i++) ydst[tid + i * 512] = ysrc[tid + i * 512];
    }
    for (int i = tid; i < 5120; i += 512) {
        int o = i >> 9, k = i & 511;
        sW7[i] = __ldg(gc7_w + k * 10 + o);
    }
    for (int i = tid; i < 2560; i += 512) sW2[i] = __ldg(mlp_w2 + i);
    if (tid < 480) sDct[tid] = g_dct[b * 480 + tid];
    __syncthreads();

    // P[m][o] = dot(y[m], w7[:,o]) with fp16 y
    #pragma unroll 1
    for (int uu = 0; uu < 30; uu++) {
        int u = uu * 16 + w;
        int m = u / 10, o = u % 10;
        const __half2* yr = (const __half2*)(sYh + m * 512);
        const float2* wr = (const float2*)(sW7 + o * 512);
        float a = 0.f;
        #pragma unroll
        for (int j = 0; j < 8; j++) {
            float2 yv = __half22float2(yr[j * 32 + lane]);
            float2 wv = wr[j * 32 + lane];
            a += yv.x * wv.x + yv.y * wv.y;
        }
        a += __shfl_xor_sync(0xFFFFFFFFu, a, 16);
        a += __shfl_xor_sync(0xFFFFFFFFu, a, 8);
        a += __shfl_xor_sync(0xFFFFFFFFu, a, 4);
        a += __shfl_xor_sync(0xFFFFFFFFu, a, 2);
        a += __shfl_xor_sync(0xFFFFFFFFu, a, 1);
        if (lane == 0) sP[u] = a;
    }
    __syncthreads();

    if (tid < 480) {
        int n = tid / 10, o = tid % 10;
        float a = __ldg(gc7_b + o) + sDct[tid];
        for (int m = 0; m < 48; m++) a += __ldg(gc7_att + n * 48 + m) * sP[m * 10 + o];
        sOut[tid] = a;
    }
    __syncthreads();

    for (int i = tid; i < 1920; i += 512) {
        int f = i % 48, t = i / 48;
        float v;
        if (t < 30) {
            v = 0.f;
            #pragma unroll
            for (int d = 0; d < 10; d++) {
                float wd = (d == 0) ? W0_DCT : W1_DCT;
                v += wd * cosf(PI_F * ((float)t + 0.5f) * (float)d / 30.0f)
                        * sOut[f * 10 + d];
            }
        } else v = g_ffc[b * 480 + f * 10 + (t - 30)];
        sFused[f * 40 + t] = v;
    }
    __syncthreads();

    {
        int o = tid & 255, fg = tid >> 8;
        float w1r[40];
        #pragma unroll
        for (int t = 0; t < 40; t++) w1r[t] = __ldg(mlp_w1 + o * 40 + t);
        for (int f = fg * 24; f < fg * 24 + 24; f++) {
            float a = 0.f;
            #pragma unroll
            for (int t = 0; t < 40; t++) a += w1r[t] * sFused[f * 40 + t];
            sH[f * 256 + o] = (a > 0.f) ? a : 0.f;
        }
    }
    __syncthreads();

    #pragma unroll 1
    for (int uu = 0; uu < 30; uu++) {
        int u = uu * 16 + w;
        int f = u / 10, t2 = u % 10;
        const float* hr = sH + f * 256;
        const float* wr = sW2 + t2 * 256;
        float a = 0.f;
        #pragma unroll
        for (int j = 0; j < 8; j++) a += hr[j * 32 + lane] * wr[j * 32 + lane];
        a += __shfl_xor_sync(0xFFFFFFFFu, a, 16);
        a += __shfl_xor_sync(0xFFFFFFFFu, a, 8);
        a += __shfl_xor_sync(0xFFFFFFFFu, a, 4);
        a += __shfl_xor_sync(0xFFFFFFFFu, a, 2);
        a += __shfl_xor_sync(0xFFFFFFFFu, a, 1);
        if (lane == 0) out[b * 480 + t2 * 48 + f] = a;
    }
}

// ===========================================================================
extern "C" void kernel_launch(void* const* d_in, const int* in_sizes, int n_in,
                              void* d_out, int out_size) {
    const float* seq     = (const float*)d_in[0];
    const float* gc1_w   = (const float*)d_in[5];
    const float* gc1_att = (const float*)d_in[6];
    const float* gc1_b   = (const float*)d_in[7];
    const float* gcb_w   = (const float*)d_in[8];
    const float* gcb_att = (const float*)d_in[9];
    const float* gcb_b   = (const float*)d_in[10];
    const float* gc7_w   = (const float*)d_in[11];
    const float* gc7_att = (const float*)d_in[12];
    const float* gc7_b   = (const float*)d_in[13];
    const float* mlp_w1  = (const float*)d_in[14];
    const float* mlp_w2  = (const float*)d_in[15];
    const float* ffc_wl  = (const float*)d_in[16];
    const float* ffc_wg  = (const float*)d_in[17];
    float* out = (float*)d_out;

    int B = in_sizes[0] / 2400;           // 1024
    int gm = (B * 48) / 96;               // 512 m-tiles

    cudaFuncSetAttribute(layer_kernel,
        cudaFuncAttributeMaxDynamicSharedMemorySize, GEMM_SMEM);
    cudaFuncSetAttribute(tail_kernel,
        cudaFuncAttributeMaxDynamicSharedMemorySize, TAIL_SMEM);

    head_kernel<<<B, 512>>>(seq, ffc_wl, ffc_wg, gc1_w, gc1_att, gc1_b, gcb_w);

    // l0: h1 -> Af only.        l1: y1 = y0 + h; writes g_X + Af.
    // l2: h2 -> Af only.        l3: y2 = y1 + h; writes Af ONLY (fp16 tail).
    for (int l = 0; l < 4; l++) {
        layer_kernel<<<dim3(4, gm), 256, GEMM_SMEM>>>(
            l, l & 1, 1, (l == 1) ? 1 : 0,
            gcb_att + l * 2304, gcb_b + l * 512);
    }
    tail_kernel<<<B, 512, TAIL_SMEM>>>(gc7_w, gc7_att, gc7_b,
                                       mlp_w1, mlp_w2, out);
}